// round 13
// baseline (speedup 1.0000x reference)
#include <cuda_runtime.h>
#include <math.h>

// ---------------------------------------------------------------------------
// YOLOX loss, B=64, A=8400, M=50, 80 classes.
// R13 = R12 + deeper latency hiding:
//   - depth-2 prefetch pipeline in phase 2 (3 stages of 2-row bundles)
//   - pos-predicated tail loads (r0..r3, matched logit) issued BEFORE phase 2,
//     consumed after (tail latency hidden under the loop)
// ---------------------------------------------------------------------------

#define NUM_A     8400
#define NUM_M     50
#define BLK       256
#define WARPS     (BLK / 32)
#define BLKS_IMG  33          // 33*256 = 8448 threads >= 8400 anchors
#define NBLOCKS   (BLKS_IMG * 64)
#define FULLMASK  0xffffffffu
#define L2E       1.4426950408889634f
#define LN2       0.6931471805599453f
#define SENT      -200.0f     // exp2f(SENT*L2E) == 0 exactly -> factor 1.0

// per (img, block): obj_sum, cls_raw, box_raw, num_pos
__device__ float    g_part[64 * BLKS_IMG * 4];
__device__ unsigned g_ticket = 0;

__device__ __forceinline__ float spl2(float x) {   // softplus(x)/ln2
    return __log2f(1.0f + exp2f(x * L2E));
}
__device__ __forceinline__ float spfac(float x) {  // 1 + e^x
    return 1.0f + exp2f(x * L2E);
}

struct RowPair {
    float v0, v1, v2, v3, v4, v5;
    int   p;
};

__device__ __forceinline__ RowPair load_pair(unsigned& pm, const float* base,
                                             int wbase, int lane) {
    RowPair o;
    o.p = -1;
    o.v0 = o.v1 = o.v2 = o.v3 = o.v4 = o.v5 = SENT;
    if (pm) {
        o.p = __ffs(pm) - 1; pm &= pm - 1;
        const float* ra = base + (size_t)(wbase + o.p) * 85;
        o.v0 = __ldg(ra + 5  + lane);
        o.v1 = __ldg(ra + 37 + lane);
        o.v2 = (lane < 16) ? __ldg(ra + 69 + lane) : SENT;
        if (pm) {
            int p1 = __ffs(pm) - 1; pm &= pm - 1;
            const float* rb = base + (size_t)(wbase + p1) * 85;
            o.v3 = __ldg(rb + 5  + lane);
            o.v4 = __ldg(rb + 37 + lane);
            o.v5 = (lane < 16) ? __ldg(rb + 69 + lane) : SENT;
        }
    }
    return o;
}

__global__ __launch_bounds__(BLK) void yolox_main_kernel(
    const float* __restrict__ pred,    // (64, 8400, 85)
    const float* __restrict__ tgt,     // (64, 50, 5)
    float* __restrict__ out)           // [5]
{
    __shared__ float2 s_ctr[NUM_M];    // compacted valid GT centers
    __shared__ float  s_x1[NUM_M], s_y1[NUM_M], s_x2[NUM_M], s_y2[NUM_M];
    __shared__ float  s_ta[NUM_M];
    __shared__ int    s_cls[NUM_M];
    __shared__ int    s_w0cnt, s_V;
    __shared__ float  s_red[WARPS][4];
    __shared__ int    s_last;

    const int img  = blockIdx.y;
    const int tid  = threadIdx.x;
    const int lane = tid & 31;
    const int warp = tid >> 5;

    // ---- load targets + ballot-prefix compaction of valid GTs ----
    float cx = 0, cy = 0, x1 = 0, y1 = 0, x2 = 0, y2 = 0, ta = 0;
    int   cls = 0, pfx = 0;
    bool  ok = false;
    if (tid < NUM_M) {
        const unsigned amask = (tid < 32) ? FULLMASK : 0x3ffffu;
        const float* tr = tgt + ((size_t)img * NUM_M + tid) * 5;
        float c = tr[0];
        ok  = (c >= 0.0f);
        cls = (int)c;
        cx = tr[1] * 640.0f; cy = tr[2] * 640.0f;
        float w = tr[3] * 640.0f, h = tr[4] * 640.0f;
        x1 = cx - w * 0.5f; y1 = cy - h * 0.5f;
        x2 = cx + w * 0.5f; y2 = cy + h * 0.5f;
        ta = (x2 - x1) * (y2 - y1);

        unsigned ball = __ballot_sync(amask, ok);
        pfx = __popc(ball & ((1u << lane) - 1u));
        if (tid == 0)  s_w0cnt = __popc(ball);
        if (tid == 32) s_V = __popc(ball);
    }
    __syncthreads();
    if (tid < NUM_M && ok) {
        int slot = pfx + ((tid < 32) ? 0 : s_w0cnt);
        s_ctr[slot] = make_float2(cx, cy);
        s_x1[slot] = x1; s_y1[slot] = y1;
        s_x2[slot] = x2; s_y2[slot] = y2;
        s_ta[slot] = ta; s_cls[slot] = cls;
    }
    if (tid == 0) s_V += s_w0cnt;
    __syncthreads();

    const int    V     = s_V;
    const int    a     = blockIdx.x * BLK + tid;
    const bool   valid = (a < NUM_A);
    const float* base  = pred + (size_t)img * NUM_A * 85;
    const float* myrow = base + (size_t)a * 85;

    // ---- early load: obj logit ----
    float pobj = 0.0f;
    if (valid) pobj = __ldg(myrow + 4);

    // ---- phase 1: magic-multiply anchor decode + packed-key argmin ----
    float ax = 0.0f, ay = 0.0f;
    if (valid) {
        // boundaries 6400/8000 are multiples of 32 -> warp-uniform branches
        if (a < 6400) {
            int r = (int)(((unsigned)a * 52429u) >> 22);       // a/80
            int c = a - r * 80;
            ax = fmaf((float)c, 8.0f, 4.0f);
            ay = fmaf((float)r, 8.0f, 4.0f);
        } else if (a < 8000) {
            int i = a - 6400;
            int r = (int)(((unsigned)i * 52429u) >> 21);       // i/40
            int c = i - r * 40;
            ax = fmaf((float)c, 16.0f, 8.0f);
            ay = fmaf((float)r, 16.0f, 8.0f);
        } else {
            int i = a - 8000;
            int r = (int)(((unsigned)i * 52429u) >> 20);       // i/20
            int c = i - r * 20;
            ax = fmaf((float)c, 32.0f, 16.0f);
            ay = fmaf((float)r, 32.0f, 16.0f);
        }
    }

    // packed key: (float_bits(d2) & ~63) | gt_index ; d2>=0 -> bit-monotone
    int k0 = 0x7f800000, k1 = 0x7f800000;   // +INF, idx 0
    int m = 0;
    for (; m + 1 < V; m += 2) {
        float2 c0 = s_ctr[m];
        float2 c1 = s_ctr[m + 1];
        float dx0 = c0.x - ax, dy0 = c0.y - ay;
        float dx1 = c1.x - ax, dy1 = c1.y - ay;
        float d20 = fmaf(dx0, dx0, dy0 * dy0);
        float d21 = fmaf(dx1, dx1, dy1 * dy1);
        int key0 = (__float_as_int(d20) & ~63) | m;
        int key1 = (__float_as_int(d21) & ~63) | (m + 1);
        k0 = min(k0, key0);
        k1 = min(k1, key1);
    }
    if (m < V) {
        float2 c0 = s_ctr[m];
        float dx0 = c0.x - ax, dy0 = c0.y - ay;
        float d20 = fmaf(dx0, dx0, dy0 * dy0);
        k0 = min(k0, (__float_as_int(d20) & ~63) | m);
    }
    int   kbest = min(k0, k1);
    int   bidx  = kbest & 63;
    float best  = __int_as_float(kbest & ~63);

    const bool  pos  = valid && (best < 4096.0f);   // DIST_THRESH_SQ
    const float posf = pos ? 1.0f : 0.0f;

    float w_obj = 0.0f;
    if (valid) w_obj = fmaf(spl2(pobj), LN2, -posf * pobj);   // bce(pobj, posf)

    // ---- early-issue tail loads (consumed after phase 2) ----
    float mlog = 0.0f, r0 = 0.0f, r1 = 0.0f, r2 = 0.0f, r3 = 0.0f;
    if (pos) {
        mlog = __ldg(myrow + 5 + s_cls[bidx]);
        r0   = __ldg(myrow + 0);
        r1   = __ldg(myrow + 1);
        r2   = __ldg(myrow + 2);
        r3   = __ldg(myrow + 3);
    }

    // ---- phase 2: 2-row grouped-log softplus, depth-2 load pipeline ----
    const int wbase = blockIdx.x * BLK + warp * 32;
    float w_cls_l2 = 0.0f;                          // log2 units

    unsigned pm = __ballot_sync(FULLMASK, pos);     // identical in all lanes
    RowPair s0 = load_pair(pm, base, wbase, lane);
    RowPair s1 = load_pair(pm, base, wbase, lane);
    while (s0.p >= 0) {
        RowPair s2 = load_pair(pm, base, wbase, lane);

        float P = spfac(s0.v0) * spfac(s0.v1) * spfac(s0.v2)
                * spfac(s0.v3) * spfac(s0.v4) * spfac(s0.v5);
        w_cls_l2 += __log2f(P);

        s0 = s1; s1 = s2;
    }
    float w_cls = w_cls_l2 * LN2;

    // ---- phase 2b + 3: matched subtract + IoU (loads long in flight) ----
    float w_box = 0.0f, w_pos = 0.0f;
    if (pos) {
        w_cls -= mlog;

        float ew = __expf(r2), eh = __expf(r3);
        float p1x = r0 - ew * 0.5f, p2x = r0 + ew * 0.5f;
        float p1y = r1 - eh * 0.5f, p2y = r1 + eh * 0.5f;
        float ix = fminf(p2x, s_x2[bidx]) - fmaxf(p1x, s_x1[bidx]);
        float iy = fminf(p2y, s_y2[bidx]) - fmaxf(p1y, s_y1[bidx]);
        float inter = fmaxf(ix, 0.0f) * fmaxf(iy, 0.0f);
        float pa    = (p2x - p1x) * (p2y - p1y);
        float uni   = pa + s_ta[bidx] - inter;
        w_box = 1.0f - inter / (uni + 1e-6f);
        w_pos = 1.0f;
    }

    // ---- reduction: warp -> block -> g_part ----
    #pragma unroll
    for (int off = 16; off; off >>= 1) {
        w_obj += __shfl_down_sync(FULLMASK, w_obj, off);
        w_cls += __shfl_down_sync(FULLMASK, w_cls, off);
        w_box += __shfl_down_sync(FULLMASK, w_box, off);
        w_pos += __shfl_down_sync(FULLMASK, w_pos, off);
    }
    if (lane == 0) {
        s_red[warp][0] = w_obj;
        s_red[warp][1] = w_cls;
        s_red[warp][2] = w_box;
        s_red[warp][3] = w_pos;
    }
    __syncthreads();

    if (tid == 0) {
        float o = 0.0f, c = 0.0f, b = 0.0f, p = 0.0f;
        #pragma unroll
        for (int i = 0; i < WARPS; i++) {
            o += s_red[i][0]; c += s_red[i][1];
            b += s_red[i][2]; p += s_red[i][3];
        }
        float* dst = g_part + ((size_t)img * BLKS_IMG + blockIdx.x) * 4;
        dst[0] = o; dst[1] = c; dst[2] = b; dst[3] = p;
        __threadfence();
        unsigned t = atomicAdd(&g_ticket, 1u);
        s_last = (t == NBLOCKS - 1) ? 1 : 0;
    }
    __syncthreads();

    // ---- last block: final reduction (deterministic values) ----
    if (s_last) {
        __shared__ float sw[8][4];
        __shared__ float sfin[4];
        const int rimg = tid >> 2;         // 0..63
        const int comp = tid & 3;          // 0=obj,1=cls,2=box,3=np

        float s = 0.0f;
        const float* p = g_part + (size_t)rimg * BLKS_IMG * 4 + comp;
        #pragma unroll
        for (int b = 0; b < BLKS_IMG; b++) s += p[b * 4];

        float np  = __shfl_sync(FULLMASK, s, lane | 3);
        float den = fmaxf(np, 1.0f);

        float v;
        if (comp == 0)      v = s / 8400.0f;
        else if (comp == 1) v = (np > 0.0f) ? s / (den * 80.0f) : 0.0f;
        else if (comp == 2) v = (np > 0.0f) ? s / den : 0.0f;
        else                v = s;

        #pragma unroll
        for (int off = 4; off < 32; off <<= 1)
            v += __shfl_down_sync(FULLMASK, v, off);

        if (lane < 4) sw[warp][lane] = v;
        __syncthreads();

        if (tid < 4) {
            float t = 0.0f;
            #pragma unroll
            for (int w = 0; w < 8; w++) t += sw[w][tid];
            sfin[tid] = t;
        }
        __syncthreads();

        if (tid == 0) {
            float obj = sfin[0], cls = sfin[1], box = sfin[2], np = sfin[3];
            out[0] = 5.0f * box + obj + cls;
            out[1] = box;
            out[2] = obj;
            out[3] = cls;
            out[4] = np;
            g_ticket = 0;      // reset for next graph replay
        }
    }
}

extern "C" void kernel_launch(void* const* d_in, const int* in_sizes, int n_in,
                              void* d_out, int out_size) {
    const float* pred = (const float*)d_in[0];
    const float* tgt  = (const float*)d_in[1];
    float* out = (float*)d_out;

    dim3 grid(BLKS_IMG, 64);
    yolox_main_kernel<<<grid, BLK>>>(pred, tgt, out);
}

// round 14
// speedup vs baseline: 1.0238x; 1.0238x over previous
#include <cuda_runtime.h>
#include <math.h>

// ---------------------------------------------------------------------------
// YOLOX loss, B=64, A=8400, M=50, 80 classes.
// R14 = R12 body, 2 anchors per thread (wave-quantization fix):
//   - 16896 -> 8448 warps: 2.07 waves -> ~1.1 (kills the ragged last wave)
//   - preamble + block reduction amortized over 2 anchors
//   - argmin shares SMEM center loads between both anchors
//   - phase 2 = R12's depth-1 load-only pipeline, run once per anchor group
// ---------------------------------------------------------------------------

#define NUM_A     8400
#define NUM_M     50
#define BLK       256
#define WARPS     (BLK / 32)
#define BLKS_IMG  17          // 17 * 512 anchors = 8704 >= 8400
#define NBLOCKS   (BLKS_IMG * 64)
#define FULLMASK  0xffffffffu
#define L2E       1.4426950408889634f
#define LN2       0.6931471805599453f
#define SENT      -200.0f     // exp2f(SENT*L2E) == 0 exactly -> factor 1.0

// per (img, block): obj_sum, cls_raw, box_raw, num_pos
__device__ float    g_part[64 * BLKS_IMG * 4];
__device__ unsigned g_ticket = 0;

__device__ __forceinline__ float spl2(float x) {   // softplus(x)/ln2
    return __log2f(1.0f + exp2f(x * L2E));
}
__device__ __forceinline__ float spfac(float x) {  // 1 + e^x
    return 1.0f + exp2f(x * L2E);
}

__device__ __forceinline__ void decode_anchor(int a, float& ax, float& ay) {
    if (a < 6400) {
        int r = (int)(((unsigned)a * 52429u) >> 22);       // a/80
        int c = a - r * 80;
        ax = fmaf((float)c, 8.0f, 4.0f);
        ay = fmaf((float)r, 8.0f, 4.0f);
    } else if (a < 8000) {
        int i = a - 6400;
        int r = (int)(((unsigned)i * 52429u) >> 21);       // i/40
        int c = i - r * 40;
        ax = fmaf((float)c, 16.0f, 8.0f);
        ay = fmaf((float)r, 16.0f, 8.0f);
    } else {
        int i = a - 8000;
        int r = (int)(((unsigned)i * 52429u) >> 20);       // i/20
        int c = i - r * 20;
        ax = fmaf((float)c, 32.0f, 16.0f);
        ay = fmaf((float)r, 32.0f, 16.0f);
    }
}

__global__ __launch_bounds__(BLK) void yolox_main_kernel(
    const float* __restrict__ pred,    // (64, 8400, 85)
    const float* __restrict__ tgt,     // (64, 50, 5)
    float* __restrict__ out)           // [5]
{
    __shared__ float2 s_ctr[NUM_M];    // compacted valid GT centers
    __shared__ float  s_x1[NUM_M], s_y1[NUM_M], s_x2[NUM_M], s_y2[NUM_M];
    __shared__ float  s_ta[NUM_M];
    __shared__ int    s_cls[NUM_M];
    __shared__ int    s_w0cnt, s_V;
    __shared__ float  s_red[WARPS][4];
    __shared__ int    s_last;

    const int img  = blockIdx.y;
    const int tid  = threadIdx.x;
    const int lane = tid & 31;
    const int warp = tid >> 5;

    // ---- load targets + ballot-prefix compaction of valid GTs ----
    float cx = 0, cy = 0, x1 = 0, y1 = 0, x2 = 0, y2 = 0, ta = 0;
    int   cls = 0, pfx = 0;
    bool  ok = false;
    if (tid < NUM_M) {
        const unsigned amask = (tid < 32) ? FULLMASK : 0x3ffffu;
        const float* tr = tgt + ((size_t)img * NUM_M + tid) * 5;
        float c = tr[0];
        ok  = (c >= 0.0f);
        cls = (int)c;
        cx = tr[1] * 640.0f; cy = tr[2] * 640.0f;
        float w = tr[3] * 640.0f, h = tr[4] * 640.0f;
        x1 = cx - w * 0.5f; y1 = cy - h * 0.5f;
        x2 = cx + w * 0.5f; y2 = cy + h * 0.5f;
        ta = (x2 - x1) * (y2 - y1);

        unsigned ball = __ballot_sync(amask, ok);
        pfx = __popc(ball & ((1u << lane) - 1u));
        if (tid == 0)  s_w0cnt = __popc(ball);
        if (tid == 32) s_V = __popc(ball);
    }
    __syncthreads();
    if (tid < NUM_M && ok) {
        int slot = pfx + ((tid < 32) ? 0 : s_w0cnt);
        s_ctr[slot] = make_float2(cx, cy);
        s_x1[slot] = x1; s_y1[slot] = y1;
        s_x2[slot] = x2; s_y2[slot] = y2;
        s_ta[slot] = ta; s_cls[slot] = cls;
    }
    if (tid == 0) s_V += s_w0cnt;
    __syncthreads();

    const int    V      = s_V;
    const int    abase  = blockIdx.x * (BLK * 2);
    const int    aA     = abase + tid;           // anchor group A
    const int    aB     = abase + BLK + tid;     // anchor group B
    const bool   validA = (aA < NUM_A);
    const bool   validB = (aB < NUM_A);
    const float* base   = pred + (size_t)img * NUM_A * 85;
    const float* rowA   = base + (size_t)aA * 85;
    const float* rowB   = base + (size_t)aB * 85;

    // ---- early loads: obj logits for both anchors ----
    float pobjA = 0.0f, pobjB = 0.0f;
    if (validA) pobjA = __ldg(rowA + 4);
    if (validB) pobjB = __ldg(rowB + 4);

    // ---- phase 1: decode both anchors, shared-center packed-key argmin ----
    float axA = 0.0f, ayA = 0.0f, axB = 0.0f, ayB = 0.0f;
    if (validA) decode_anchor(aA, axA, ayA);
    if (validB) decode_anchor(aB, axB, ayB);

    int kA0 = 0x7f800000, kA1 = 0x7f800000;
    int kB0 = 0x7f800000, kB1 = 0x7f800000;
    int m = 0;
    for (; m + 1 < V; m += 2) {
        float2 c0 = s_ctr[m];
        float2 c1 = s_ctr[m + 1];
        float dxA0 = c0.x - axA, dyA0 = c0.y - ayA;
        float dxA1 = c1.x - axA, dyA1 = c1.y - ayA;
        float dxB0 = c0.x - axB, dyB0 = c0.y - ayB;
        float dxB1 = c1.x - axB, dyB1 = c1.y - ayB;
        float dA0 = fmaf(dxA0, dxA0, dyA0 * dyA0);
        float dA1 = fmaf(dxA1, dxA1, dyA1 * dyA1);
        float dB0 = fmaf(dxB0, dxB0, dyB0 * dyB0);
        float dB1 = fmaf(dxB1, dxB1, dyB1 * dyB1);
        kA0 = min(kA0, (__float_as_int(dA0) & ~63) | m);
        kA1 = min(kA1, (__float_as_int(dA1) & ~63) | (m + 1));
        kB0 = min(kB0, (__float_as_int(dB0) & ~63) | m);
        kB1 = min(kB1, (__float_as_int(dB1) & ~63) | (m + 1));
    }
    if (m < V) {
        float2 c0 = s_ctr[m];
        float dxA0 = c0.x - axA, dyA0 = c0.y - ayA;
        float dxB0 = c0.x - axB, dyB0 = c0.y - ayB;
        float dA0 = fmaf(dxA0, dxA0, dyA0 * dyA0);
        float dB0 = fmaf(dxB0, dxB0, dyB0 * dyB0);
        kA0 = min(kA0, (__float_as_int(dA0) & ~63) | m);
        kB0 = min(kB0, (__float_as_int(dB0) & ~63) | m);
    }
    int   kA = min(kA0, kA1),              kB = min(kB0, kB1);
    int   bidxA = kA & 63,                 bidxB = kB & 63;
    float bestA = __int_as_float(kA & ~63), bestB = __int_as_float(kB & ~63);

    const bool  posA  = validA && (bestA < 4096.0f);
    const bool  posB  = validB && (bestB < 4096.0f);
    const float posfA = posA ? 1.0f : 0.0f;
    const float posfB = posB ? 1.0f : 0.0f;

    float w_obj = 0.0f;
    if (validA) w_obj  = fmaf(spl2(pobjA), LN2, -posfA * pobjA);
    if (validB) w_obj += fmaf(spl2(pobjB), LN2, -posfB * pobjB);

    // ---- phase 2: R12 depth-1 pipeline, run for both anchor groups ----
    float w_cls_l2 = 0.0f;

    #pragma unroll
    for (int g = 0; g < 2; g++) {
        const bool mypos = (g == 0) ? posA : posB;
        const int  wbase = abase + g * BLK + warp * 32;
        unsigned pm = __ballot_sync(FULLMASK, mypos);   // identical in all lanes

        int   p0 = -1;
        float A0 = SENT, A1 = SENT, A2 = SENT;
        float B0 = SENT, B1 = SENT, B2 = SENT;
        if (pm) {
            p0 = __ffs(pm) - 1; pm &= pm - 1;
            const float* ra = base + (size_t)(wbase + p0) * 85;
            A0 = __ldg(ra + 5  + lane);
            A1 = __ldg(ra + 37 + lane);
            A2 = (lane < 16) ? __ldg(ra + 69 + lane) : SENT;
            if (pm) {
                int p1 = __ffs(pm) - 1; pm &= pm - 1;
                const float* rb = base + (size_t)(wbase + p1) * 85;
                B0 = __ldg(rb + 5  + lane);
                B1 = __ldg(rb + 37 + lane);
                B2 = (lane < 16) ? __ldg(rb + 69 + lane) : SENT;
            }
        }
        while (p0 >= 0) {
            int   n0 = -1;
            float C0 = SENT, C1 = SENT, C2 = SENT;
            float D0 = SENT, D1 = SENT, D2 = SENT;
            if (pm) {
                n0 = __ffs(pm) - 1; pm &= pm - 1;
                const float* ra = base + (size_t)(wbase + n0) * 85;
                C0 = __ldg(ra + 5  + lane);
                C1 = __ldg(ra + 37 + lane);
                C2 = (lane < 16) ? __ldg(ra + 69 + lane) : SENT;
                if (pm) {
                    int n1 = __ffs(pm) - 1; pm &= pm - 1;
                    const float* rb = base + (size_t)(wbase + n1) * 85;
                    D0 = __ldg(rb + 5  + lane);
                    D1 = __ldg(rb + 37 + lane);
                    D2 = (lane < 16) ? __ldg(rb + 69 + lane) : SENT;
                }
            }

            float P = spfac(A0) * spfac(A1) * spfac(A2)
                    * spfac(B0) * spfac(B1) * spfac(B2);
            w_cls_l2 += __log2f(P);

            p0 = n0;
            A0 = C0; A1 = C1; A2 = C2;
            B0 = D0; B1 = D1; B2 = D2;
        }
    }
    float w_cls = w_cls_l2 * LN2;

    // ---- phase 2b + 3: matched subtract + IoU per anchor (L1 hits) ----
    float w_box = 0.0f, w_pos = 0.0f;
    if (posA) {
        w_cls -= __ldg(rowA + 5 + s_cls[bidxA]);
        float r0 = __ldg(rowA + 0), r1 = __ldg(rowA + 1);
        float r2 = __ldg(rowA + 2), r3 = __ldg(rowA + 3);
        float ew = __expf(r2), eh = __expf(r3);
        float p1x = r0 - ew * 0.5f, p2x = r0 + ew * 0.5f;
        float p1y = r1 - eh * 0.5f, p2y = r1 + eh * 0.5f;
        float ix = fminf(p2x, s_x2[bidxA]) - fmaxf(p1x, s_x1[bidxA]);
        float iy = fminf(p2y, s_y2[bidxA]) - fmaxf(p1y, s_y1[bidxA]);
        float inter = fmaxf(ix, 0.0f) * fmaxf(iy, 0.0f);
        float pa    = (p2x - p1x) * (p2y - p1y);
        float uni   = pa + s_ta[bidxA] - inter;
        w_box += 1.0f - inter / (uni + 1e-6f);
        w_pos += 1.0f;
    }
    if (posB) {
        w_cls -= __ldg(rowB + 5 + s_cls[bidxB]);
        float r0 = __ldg(rowB + 0), r1 = __ldg(rowB + 1);
        float r2 = __ldg(rowB + 2), r3 = __ldg(rowB + 3);
        float ew = __expf(r2), eh = __expf(r3);
        float p1x = r0 - ew * 0.5f, p2x = r0 + ew * 0.5f;
        float p1y = r1 - eh * 0.5f, p2y = r1 + eh * 0.5f;
        float ix = fminf(p2x, s_x2[bidxB]) - fmaxf(p1x, s_x1[bidxB]);
        float iy = fminf(p2y, s_y2[bidxB]) - fmaxf(p1y, s_y1[bidxB]);
        float inter = fmaxf(ix, 0.0f) * fmaxf(iy, 0.0f);
        float pa    = (p2x - p1x) * (p2y - p1y);
        float uni   = pa + s_ta[bidxB] - inter;
        w_box += 1.0f - inter / (uni + 1e-6f);
        w_pos += 1.0f;
    }

    // ---- reduction: warp -> block -> g_part ----
    #pragma unroll
    for (int off = 16; off; off >>= 1) {
        w_obj += __shfl_down_sync(FULLMASK, w_obj, off);
        w_cls += __shfl_down_sync(FULLMASK, w_cls, off);
        w_box += __shfl_down_sync(FULLMASK, w_box, off);
        w_pos += __shfl_down_sync(FULLMASK, w_pos, off);
    }
    if (lane == 0) {
        s_red[warp][0] = w_obj;
        s_red[warp][1] = w_cls;
        s_red[warp][2] = w_box;
        s_red[warp][3] = w_pos;
    }
    __syncthreads();

    if (tid == 0) {
        float o = 0.0f, c = 0.0f, b = 0.0f, p = 0.0f;
        #pragma unroll
        for (int i = 0; i < WARPS; i++) {
            o += s_red[i][0]; c += s_red[i][1];
            b += s_red[i][2]; p += s_red[i][3];
        }
        float* dst = g_part + ((size_t)img * BLKS_IMG + blockIdx.x) * 4;
        dst[0] = o; dst[1] = c; dst[2] = b; dst[3] = p;
        __threadfence();
        unsigned t = atomicAdd(&g_ticket, 1u);
        s_last = (t == NBLOCKS - 1) ? 1 : 0;
    }
    __syncthreads();

    // ---- last block: final reduction (deterministic values) ----
    if (s_last) {
        __shared__ float sw[8][4];
        __shared__ float sfin[4];
        const int rimg = tid >> 2;         // 0..63
        const int comp = tid & 3;          // 0=obj,1=cls,2=box,3=np

        float s = 0.0f;
        const float* p = g_part + (size_t)rimg * BLKS_IMG * 4 + comp;
        #pragma unroll
        for (int b = 0; b < BLKS_IMG; b++) s += p[b * 4];

        float np  = __shfl_sync(FULLMASK, s, lane | 3);
        float den = fmaxf(np, 1.0f);

        float v;
        if (comp == 0)      v = s / 8400.0f;
        else if (comp == 1) v = (np > 0.0f) ? s / (den * 80.0f) : 0.0f;
        else if (comp == 2) v = (np > 0.0f) ? s / den : 0.0f;
        else                v = s;

        #pragma unroll
        for (int off = 4; off < 32; off <<= 1)
            v += __shfl_down_sync(FULLMASK, v, off);

        if (lane < 4) sw[warp][lane] = v;
        __syncthreads();

        if (tid < 4) {
            float t = 0.0f;
            #pragma unroll
            for (int w = 0; w < 8; w++) t += sw[w][tid];
            sfin[tid] = t;
        }
        __syncthreads();

        if (tid == 0) {
            float obj = sfin[0], cls = sfin[1], box = sfin[2], np = sfin[3];
            out[0] = 5.0f * box + obj + cls;
            out[1] = box;
            out[2] = obj;
            out[3] = cls;
            out[4] = np;
            g_ticket = 0;      // reset for next graph replay
        }
    }
}

extern "C" void kernel_launch(void* const* d_in, const int* in_sizes, int n_in,
                              void* d_out, int out_size) {
    const float* pred = (const float*)d_in[0];
    const float* tgt  = (const float*)d_in[1];
    float* out = (float*)d_out;

    dim3 grid(BLKS_IMG, 64);
    yolox_main_kernel<<<grid, BLK>>>(pred, tgt, out);
}

// round 15
// speedup vs baseline: 1.1883x; 1.1607x over previous
#include <cuda_runtime.h>
#include <math.h>

// ---------------------------------------------------------------------------
// YOLOX loss, B=64, A=8400, M=50, 80 classes.
// R15 = R12 + block-pooled positive-row queue:
//   - all positive rows of the block compacted into a SMEM list (ballot +
//     per-warp prefix); warps consume slots round-robin -> per-warp load
//     balance to +-1 row (was binomial, block waits on slowest warp)
//   - in-loop ffs/mask bookkeeping replaced by LDS index fetch
//   - everything else identical to R12 (best known: depth-1 load-only
//     prefetch, grouped-log softplus, packed-key argmin, magic decode)
// ---------------------------------------------------------------------------

#define NUM_A     8400
#define NUM_M     50
#define BLK       256
#define WARPS     (BLK / 32)
#define BLKS_IMG  33          // 33*256 = 8448 threads >= 8400 anchors
#define NBLOCKS   (BLKS_IMG * 64)
#define FULLMASK  0xffffffffu
#define L2E       1.4426950408889634f
#define LN2       0.6931471805599453f
#define SENT      -200.0f     // exp2f(SENT*L2E) == 0 exactly -> factor 1.0

// per (img, block): obj_sum, cls_raw, box_raw, num_pos
__device__ float    g_part[64 * BLKS_IMG * 4];
__device__ unsigned g_ticket = 0;

__device__ __forceinline__ float spl2(float x) {   // softplus(x)/ln2
    return __log2f(1.0f + exp2f(x * L2E));
}
__device__ __forceinline__ float spfac(float x) {  // 1 + e^x
    return 1.0f + exp2f(x * L2E);
}

__global__ __launch_bounds__(BLK) void yolox_main_kernel(
    const float* __restrict__ pred,    // (64, 8400, 85)
    const float* __restrict__ tgt,     // (64, 50, 5)
    float* __restrict__ out)           // [5]
{
    __shared__ float2 s_ctr[NUM_M];    // compacted valid GT centers
    __shared__ float  s_x1[NUM_M], s_y1[NUM_M], s_x2[NUM_M], s_y2[NUM_M];
    __shared__ float  s_ta[NUM_M];
    __shared__ int    s_cls[NUM_M];
    __shared__ int    s_w0cnt, s_V;
    __shared__ float  s_red[WARPS][4];
    __shared__ int    s_last;
    __shared__ int            s_wcnt[WARPS];   // positives per warp
    __shared__ unsigned char  s_list[BLK];     // block-local positive rows

    const int img  = blockIdx.y;
    const int tid  = threadIdx.x;
    const int lane = tid & 31;
    const int warp = tid >> 5;

    // ---- load targets + ballot-prefix compaction of valid GTs ----
    float cx = 0, cy = 0, x1 = 0, y1 = 0, x2 = 0, y2 = 0, ta = 0;
    int   cls = 0, pfx = 0;
    bool  ok = false;
    if (tid < NUM_M) {
        const unsigned amask = (tid < 32) ? FULLMASK : 0x3ffffu;
        const float* tr = tgt + ((size_t)img * NUM_M + tid) * 5;
        float c = tr[0];
        ok  = (c >= 0.0f);
        cls = (int)c;
        cx = tr[1] * 640.0f; cy = tr[2] * 640.0f;
        float w = tr[3] * 640.0f, h = tr[4] * 640.0f;
        x1 = cx - w * 0.5f; y1 = cy - h * 0.5f;
        x2 = cx + w * 0.5f; y2 = cy + h * 0.5f;
        ta = (x2 - x1) * (y2 - y1);

        unsigned ball = __ballot_sync(amask, ok);
        pfx = __popc(ball & ((1u << lane) - 1u));
        if (tid == 0)  s_w0cnt = __popc(ball);
        if (tid == 32) s_V = __popc(ball);
    }
    __syncthreads();
    if (tid < NUM_M && ok) {
        int slot = pfx + ((tid < 32) ? 0 : s_w0cnt);
        s_ctr[slot] = make_float2(cx, cy);
        s_x1[slot] = x1; s_y1[slot] = y1;
        s_x2[slot] = x2; s_y2[slot] = y2;
        s_ta[slot] = ta; s_cls[slot] = cls;
    }
    if (tid == 0) s_V += s_w0cnt;
    __syncthreads();

    const int    V     = s_V;
    const int    a     = blockIdx.x * BLK + tid;
    const bool   valid = (a < NUM_A);
    const float* base  = pred + (size_t)img * NUM_A * 85;
    const float* myrow = base + (size_t)a * 85;

    // ---- early load: obj logit ----
    float pobj = 0.0f;
    if (valid) pobj = __ldg(myrow + 4);

    // ---- phase 1: magic-multiply anchor decode + packed-key argmin ----
    float ax = 0.0f, ay = 0.0f;
    if (valid) {
        if (a < 6400) {
            int r = (int)(((unsigned)a * 52429u) >> 22);       // a/80
            int c = a - r * 80;
            ax = fmaf((float)c, 8.0f, 4.0f);
            ay = fmaf((float)r, 8.0f, 4.0f);
        } else if (a < 8000) {
            int i = a - 6400;
            int r = (int)(((unsigned)i * 52429u) >> 21);       // i/40
            int c = i - r * 40;
            ax = fmaf((float)c, 16.0f, 8.0f);
            ay = fmaf((float)r, 16.0f, 8.0f);
        } else {
            int i = a - 8000;
            int r = (int)(((unsigned)i * 52429u) >> 20);       // i/20
            int c = i - r * 20;
            ax = fmaf((float)c, 32.0f, 16.0f);
            ay = fmaf((float)r, 32.0f, 16.0f);
        }
    }

    // packed key: (float_bits(d2) & ~63) | gt_index ; d2>=0 -> bit-monotone
    int k0 = 0x7f800000, k1 = 0x7f800000;   // +INF, idx 0
    int m = 0;
    for (; m + 1 < V; m += 2) {
        float2 c0 = s_ctr[m];
        float2 c1 = s_ctr[m + 1];
        float dx0 = c0.x - ax, dy0 = c0.y - ay;
        float dx1 = c1.x - ax, dy1 = c1.y - ay;
        float d20 = fmaf(dx0, dx0, dy0 * dy0);
        float d21 = fmaf(dx1, dx1, dy1 * dy1);
        k0 = min(k0, (__float_as_int(d20) & ~63) | m);
        k1 = min(k1, (__float_as_int(d21) & ~63) | (m + 1));
    }
    if (m < V) {
        float2 c0 = s_ctr[m];
        float dx0 = c0.x - ax, dy0 = c0.y - ay;
        float d20 = fmaf(dx0, dx0, dy0 * dy0);
        k0 = min(k0, (__float_as_int(d20) & ~63) | m);
    }
    int   kbest = min(k0, k1);
    int   bidx  = kbest & 63;
    float best  = __int_as_float(kbest & ~63);

    const bool  pos  = valid && (best < 4096.0f);   // DIST_THRESH_SQ
    const float posf = pos ? 1.0f : 0.0f;

    float w_obj = 0.0f;
    if (valid) w_obj = fmaf(spl2(pobj), LN2, -posf * pobj);   // bce(pobj, posf)

    // ---- build block-pooled positive-row list ----
    unsigned pm = __ballot_sync(FULLMASK, pos);
    if (lane == 0) s_wcnt[warp] = __popc(pm);
    __syncthreads();

    int off = 0, total = 0;
    #pragma unroll
    for (int i = 0; i < WARPS; i++) {
        int c = s_wcnt[i];
        if (i < warp) off += c;
        total += c;
    }
    if (pos) {
        int ppfx = __popc(pm & ((1u << lane) - 1u));
        s_list[off + ppfx] = (unsigned char)tid;
    }
    __syncthreads();

    // ---- phase 2: pooled grouped-log softplus, depth-1 load pipeline ----
    // warp consumes slots warp, warp+8, warp+16, ... (balanced +-1)
    const int ablk = blockIdx.x * BLK;
    float w_cls_l2 = 0.0f;                          // log2 units

    int ka = warp, kb = warp + WARPS;
    float A0 = SENT, A1 = SENT, A2 = SENT;
    float B0 = SENT, B1 = SENT, B2 = SENT;
    if (ka < total) {
        const float* ra = base + (size_t)(ablk + s_list[ka]) * 85;
        A0 = __ldg(ra + 5  + lane);
        A1 = __ldg(ra + 37 + lane);
        A2 = (lane < 16) ? __ldg(ra + 69 + lane) : SENT;
        if (kb < total) {
            const float* rb = base + (size_t)(ablk + s_list[kb]) * 85;
            B0 = __ldg(rb + 5  + lane);
            B1 = __ldg(rb + 37 + lane);
            B2 = (lane < 16) ? __ldg(rb + 69 + lane) : SENT;
        }
    }
    while (ka < total) {
        int na = ka + 2 * WARPS, nb = kb + 2 * WARPS;
        float C0 = SENT, C1 = SENT, C2 = SENT;
        float D0 = SENT, D1 = SENT, D2 = SENT;
        if (na < total) {
            const float* ra = base + (size_t)(ablk + s_list[na]) * 85;
            C0 = __ldg(ra + 5  + lane);
            C1 = __ldg(ra + 37 + lane);
            C2 = (lane < 16) ? __ldg(ra + 69 + lane) : SENT;
            if (nb < total) {
                const float* rb = base + (size_t)(ablk + s_list[nb]) * 85;
                D0 = __ldg(rb + 5  + lane);
                D1 = __ldg(rb + 37 + lane);
                D2 = (lane < 16) ? __ldg(rb + 69 + lane) : SENT;
            }
        }

        float P = spfac(A0) * spfac(A1) * spfac(A2)
                * spfac(B0) * spfac(B1) * spfac(B2);
        w_cls_l2 += __log2f(P);

        ka = na; kb = nb;
        A0 = C0; A1 = C1; A2 = C2;
        B0 = D0; B1 = D1; B2 = D2;
    }
    float w_cls = w_cls_l2 * LN2;

    // ---- phase 2b + 3: matched subtract + IoU (own anchor; L1/L2 hits) ----
    float w_box = 0.0f, w_pos = 0.0f;
    if (pos) {
        w_cls -= __ldg(myrow + 5 + s_cls[bidx]);

        float r0 = __ldg(myrow + 0);
        float r1 = __ldg(myrow + 1);
        float r2 = __ldg(myrow + 2);
        float r3 = __ldg(myrow + 3);
        float ew = __expf(r2), eh = __expf(r3);
        float p1x = r0 - ew * 0.5f, p2x = r0 + ew * 0.5f;
        float p1y = r1 - eh * 0.5f, p2y = r1 + eh * 0.5f;
        float ix = fminf(p2x, s_x2[bidx]) - fmaxf(p1x, s_x1[bidx]);
        float iy = fminf(p2y, s_y2[bidx]) - fmaxf(p1y, s_y1[bidx]);
        float inter = fmaxf(ix, 0.0f) * fmaxf(iy, 0.0f);
        float pa    = (p2x - p1x) * (p2y - p1y);
        float uni   = pa + s_ta[bidx] - inter;
        w_box = 1.0f - inter / (uni + 1e-6f);
        w_pos = 1.0f;
    }

    // ---- reduction: warp -> block -> g_part ----
    #pragma unroll
    for (int off2 = 16; off2; off2 >>= 1) {
        w_obj += __shfl_down_sync(FULLMASK, w_obj, off2);
        w_cls += __shfl_down_sync(FULLMASK, w_cls, off2);
        w_box += __shfl_down_sync(FULLMASK, w_box, off2);
        w_pos += __shfl_down_sync(FULLMASK, w_pos, off2);
    }
    if (lane == 0) {
        s_red[warp][0] = w_obj;
        s_red[warp][1] = w_cls;
        s_red[warp][2] = w_box;
        s_red[warp][3] = w_pos;
    }
    __syncthreads();

    if (tid == 0) {
        float o = 0.0f, c = 0.0f, b = 0.0f, p = 0.0f;
        #pragma unroll
        for (int i = 0; i < WARPS; i++) {
            o += s_red[i][0]; c += s_red[i][1];
            b += s_red[i][2]; p += s_red[i][3];
        }
        float* dst = g_part + ((size_t)img * BLKS_IMG + blockIdx.x) * 4;
        dst[0] = o; dst[1] = c; dst[2] = b; dst[3] = p;
        __threadfence();
        unsigned t = atomicAdd(&g_ticket, 1u);
        s_last = (t == NBLOCKS - 1) ? 1 : 0;
    }
    __syncthreads();

    // ---- last block: final reduction (deterministic values) ----
    if (s_last) {
        __shared__ float sw[8][4];
        __shared__ float sfin[4];
        const int rimg = tid >> 2;         // 0..63
        const int comp = tid & 3;          // 0=obj,1=cls,2=box,3=np

        float s = 0.0f;
        const float* p = g_part + (size_t)rimg * BLKS_IMG * 4 + comp;
        #pragma unroll
        for (int b = 0; b < BLKS_IMG; b++) s += p[b * 4];

        float np  = __shfl_sync(FULLMASK, s, lane | 3);
        float den = fmaxf(np, 1.0f);

        float v;
        if (comp == 0)      v = s / 8400.0f;
        else if (comp == 1) v = (np > 0.0f) ? s / (den * 80.0f) : 0.0f;
        else if (comp == 2) v = (np > 0.0f) ? s / den : 0.0f;
        else                v = s;

        #pragma unroll
        for (int off2 = 4; off2 < 32; off2 <<= 1)
            v += __shfl_down_sync(FULLMASK, v, off2);

        if (lane < 4) sw[warp][lane] = v;
        __syncthreads();

        if (tid < 4) {
            float t = 0.0f;
            #pragma unroll
            for (int w = 0; w < 8; w++) t += sw[w][tid];
            sfin[tid] = t;
        }
        __syncthreads();

        if (tid == 0) {
            float obj = sfin[0], cls = sfin[1], box = sfin[2], np = sfin[3];
            out[0] = 5.0f * box + obj + cls;
            out[1] = box;
            out[2] = obj;
            out[3] = cls;
            out[4] = np;
            g_ticket = 0;      // reset for next graph replay
        }
    }
}

extern "C" void kernel_launch(void* const* d_in, const int* in_sizes, int n_in,
                              void* d_out, int out_size) {
    const float* pred = (const float*)d_in[0];
    const float* tgt  = (const float*)d_in[1];
    float* out = (float*)d_out;

    dim3 grid(BLKS_IMG, 64);
    yolox_main_kernel<<<grid, BLK>>>(pred, tgt, out);
}